// round 9
// baseline (speedup 1.0000x reference)
#include <cuda_runtime.h>
#include <cuda_fp16.h>
#include <cstdint>

// ---------------- problem constants ----------------
#define BATCH 2
#define NPOS  8000          // 20*20*20
#define NQT   63            // ceil(8000/128); tail tile has exactly 64 keys

// -------- device scratch (padded: tail tile cp.async reads up to row 8063;
//          pad region is never written -> stays zero, and tail key-half-1
//          warps skip compute, so zeros never pollute softmax) --------
__device__ __half g_Qh[BATCH * NPOS * 64];          // (b, n, k) pre-scaled
__device__ __half g_Kh[BATCH * NPOS * 64 + 8192];   // (b, n, k)
__device__ __half g_Vt[BATCH * 64 * NPOS + 8192];   // (b, c, n) transposed
__device__ float  g_O [BATCH * NPOS * 64];          // (b, n, c) fp32

#define QSCALE (0.125f * 1.44269504f)   // 1/sqrt(64) * log2(e), folded into Q
#define ONES_H2 0x3C003C00u             // f16x2 {1.0, 1.0}

// ---------------- PTX helpers ----------------
__device__ __forceinline__ uint32_t smem_u32(const void* p) {
    uint32_t a;
    asm("{ .reg .u64 t; cvta.to.shared.u64 t, %1; cvt.u32.u64 %0, t; }"
        : "=r"(a) : "l"(p));
    return a;
}

__device__ __forceinline__ void mma_f16(float d[4], const uint32_t a[4],
                                        const uint32_t b0, const uint32_t b1,
                                        const float c[4]) {
    asm volatile(
        "mma.sync.aligned.m16n8k16.row.col.f32.f16.f16.f32 "
        "{%0,%1,%2,%3}, {%4,%5,%6,%7}, {%8,%9}, {%10,%11,%12,%13};"
        : "=f"(d[0]), "=f"(d[1]), "=f"(d[2]), "=f"(d[3])
        : "r"(a[0]), "r"(a[1]), "r"(a[2]), "r"(a[3]),
          "r"(b0), "r"(b1),
          "f"(c[0]), "f"(c[1]), "f"(c[2]), "f"(c[3]));
}

__device__ __forceinline__ void mma_f16h(uint32_t d[2], const uint32_t a[4],
                                         const uint32_t b0, const uint32_t b1,
                                         const uint32_t c0, const uint32_t c1) {
    asm volatile(
        "mma.sync.aligned.m16n8k16.row.col.f16.f16.f16.f16 "
        "{%0,%1}, {%2,%3,%4,%5}, {%6,%7}, {%8,%9};"
        : "=r"(d[0]), "=r"(d[1])
        : "r"(a[0]), "r"(a[1]), "r"(a[2]), "r"(a[3]),
          "r"(b0), "r"(b1), "r"(c0), "r"(c1));
}

__device__ __forceinline__ void ldsm4(uint32_t& d0, uint32_t& d1,
                                      uint32_t& d2, uint32_t& d3, uint32_t addr) {
    asm volatile("ldmatrix.sync.aligned.m8n8.x4.shared.b16 {%0,%1,%2,%3}, [%4];"
                 : "=r"(d0), "=r"(d1), "=r"(d2), "=r"(d3) : "r"(addr));
}

__device__ __forceinline__ uint32_t ex2h2(uint32_t h) {
    uint32_t r;
    asm("ex2.approx.f16x2 %0, %1;" : "=r"(r) : "r"(h));
    return r;
}

__device__ __forceinline__ void cpasync16(uint32_t dst, const void* src) {
    asm volatile("cp.async.cg.shared.global [%0], [%1], 16;" :: "r"(dst), "l"(src));
}
#define CP_COMMIT() asm volatile("cp.async.commit_group;" ::: "memory")

// ============================================================================
// Kernel A: fused QKV projection (unchanged from round 8, 28.7us).
// ============================================================================
#define QKV2_SMEM_FLOATS (192 * 64 + 192 + 128 * 68)   // 84,736 B

__global__ __launch_bounds__(512) void qkv_kernel(
    const float* __restrict__ x,
    const float* __restrict__ wq, const float* __restrict__ bq,
    const float* __restrict__ wk, const float* __restrict__ bk,
    const float* __restrict__ wv, const float* __restrict__ bv)
{
    extern __shared__ float sm[];
    float* Ws = sm;
    float* bs = Ws + 192 * 64;
    float* xs = bs + 192;
    __half* stage = (__half*)sm;

    const int tid = threadIdx.x;
    const int b   = blockIdx.y;
    const int n0  = blockIdx.x * 128;

    for (int i = tid; i < 4096; i += 512) {
        Ws[i] = wq[i]; Ws[4096 + i] = wk[i]; Ws[8192 + i] = wv[i];
    }
    if (tid < 64) { bs[tid] = bq[tid]; bs[64 + tid] = bk[tid]; bs[128 + tid] = bv[tid]; }
    for (int i = tid; i < 128 * 64; i += 512) {
        int c = i >> 7, nn = i & 127;
        float v = (n0 + nn < NPOS) ? x[(b * 64 + c) * NPOS + n0 + nn] : 0.f;
        xs[nn * 68 + c] = v;
    }
    __syncthreads();

    const int pq = tid & 31;
    const int o0 = (tid >> 5) * 12;

    float acc[4][12];
#pragma unroll
    for (int p = 0; p < 4; ++p)
#pragma unroll
        for (int j = 0; j < 12; ++j) acc[p][j] = 0.f;

#pragma unroll 4
    for (int c = 0; c < 64; c += 4) {
        float4 xv[4];
#pragma unroll
        for (int p = 0; p < 4; ++p)
            xv[p] = *(const float4*)&xs[(pq + 32 * p) * 68 + c];
#pragma unroll
        for (int j = 0; j < 12; ++j) {
            float4 w4 = *(const float4*)&Ws[(o0 + j) * 64 + c];
#pragma unroll
            for (int p = 0; p < 4; ++p) {
                acc[p][j] += w4.x * xv[p].x + w4.y * xv[p].y
                           + w4.z * xv[p].z + w4.w * xv[p].w;
            }
        }
    }
    __syncthreads();

#pragma unroll
    for (int j = 0; j < 12; ++j) {
        int o = o0 + j;
        if (o < 64) {
#pragma unroll
            for (int p = 0; p < 4; ++p)
                stage[(pq + 32 * p) * 72 + o] =
                    __float2half_rn((acc[p][j] + bs[o]) * QSCALE);
        }
    }
    __syncthreads();
    for (int i = tid; i < 1024; i += 512) {
        int r = i >> 3, c8 = (i & 7) << 3;
        if (n0 + r < NPOS)
            *(uint4*)&g_Qh[((b * NPOS) + n0 + r) * 64 + c8] =
                *(const uint4*)&stage[r * 72 + c8];
    }
    __syncthreads();

#pragma unroll
    for (int j = 0; j < 12; ++j) {
        int o = o0 + j;
        if (o >= 64 && o < 128) {
#pragma unroll
            for (int p = 0; p < 4; ++p)
                stage[(pq + 32 * p) * 72 + (o - 64)] =
                    __float2half_rn(acc[p][j] + bs[o]);
        }
    }
    __syncthreads();
    for (int i = tid; i < 1024; i += 512) {
        int r = i >> 3, c8 = (i & 7) << 3;
        if (n0 + r < NPOS)
            *(uint4*)&g_Kh[((b * NPOS) + n0 + r) * 64 + c8] =
                *(const uint4*)&stage[r * 72 + c8];
    }
    __syncthreads();

#pragma unroll
    for (int j = 0; j < 12; ++j) {
        int o = o0 + j;
        if (o >= 128) {
#pragma unroll
            for (int p = 0; p < 4; ++p)
                stage[(o - 128) * 136 + pq + 32 * p] =
                    __float2half_rn(acc[p][j] + bs[o]);
        }
    }
    __syncthreads();
    for (int i = tid; i < 1024; i += 512) {
        int r = i >> 4, p8 = (i & 15) << 3;
        if (n0 + p8 < NPOS)
            *(uint4*)&g_Vt[((b * 64) + r) * NPOS + n0 + p8] =
                *(const uint4*)&stage[r * 136 + p8];
    }
}

// ============================================================================
// Kernel B: flash attention, key-split across 16 warps (512 threads).
//   Warp w: Q rows (w&7)*16..+16, key half (w>>3)*64..+64 of each tile.
//   Fixed-reference softmax -> partial O / row sums over disjoint key ranges
//   combine by addition once at the end (smem reduction, reusing K stages).
// ============================================================================
#define QSTW 36                 // Q/K row stride in words (72 f16)
#define VSTW 68                 // V row stride in words (136 f16)
#define KTILE_W (128 * QSTW)
#define VTILE_W (64 * VSTW)
#define FLASH_SMEM_BYTES ((128 * QSTW + 2 * KTILE_W + 2 * VTILE_W) * 4)  // 90,112

__global__ __launch_bounds__(512, 1) void flash_mma_kernel()
{
    extern __shared__ uint32_t smw[];
    uint32_t* Qw = smw;                              // [128][36]
    const uint32_t sbase  = smem_u32(smw);
    const uint32_t kbase0 = sbase + 128 * QSTW * 4;
    const uint32_t vbase0 = kbase0 + 2 * KTILE_W * 4;

    const int tid  = threadIdx.x;
    const int wid  = tid >> 5, lane = tid & 31;
    const int g    = lane >> 2, tig = lane & 3;
    const int b    = blockIdx.y;
    const int n0   = blockIdx.x * 128;
    const int qrows = min(128, NPOS - n0);
    const int rw   = wid & 7;           // row-group
    const int kh   = wid >> 3;          // key half (0: keys 0-63, 1: 64-127)
    const int rb   = rw * 16;

    // ---- Q tile ----
    for (int idx = tid; idx < 128 * 8; idx += 512) {
        int r = idx >> 3, c8 = (idx & 7) << 3;
        uint4 v = make_uint4(0u, 0u, 0u, 0u);
        if (r < qrows) v = *(const uint4*)&g_Qh[((b * NPOS) + n0 + r) * 64 + c8];
        *(uint4*)&Qw[r * QSTW + (c8 >> 1)] = v;
    }
    __syncthreads();

    uint32_t qa[4][4];
#pragma unroll
    for (int k = 0; k < 4; ++k) {
        qa[k][0] = Qw[(rb + g    ) * QSTW + 8 * k + tig];
        qa[k][1] = Qw[(rb + g + 8) * QSTW + 8 * k + tig];
        qa[k][2] = Qw[(rb + g    ) * QSTW + 8 * k + tig + 4];
        qa[k][3] = Qw[(rb + g + 8) * QSTW + 8 * k + tig + 4];
    }

    // ldmatrix per-lane offsets; key-half offsets folded in:
    //   K: half kh starts at row kh*64 -> + kh*64*QSTW words
    //   V: half kh starts at key kh*64 -> + kh*32 words (2 keys/word)
    const int row_in = (lane & 7) | ((lane >> 4) << 3);
    const int woff   = ((lane >> 3) & 1) << 2;
    const uint32_t kLane = (uint32_t)(((row_in + kh * 64) * QSTW + woff) * 4);
    const uint32_t vLane = (uint32_t)((row_in * VSTW + woff + kh * 32) * 4);

    float ofrag[9][4];                 // [0..7]: O chans; [8]: row sums
#pragma unroll
    for (int nb = 0; nb < 9; ++nb)
#pragma unroll
        for (int i = 0; i < 4; ++i) ofrag[nb][i] = 0.f;

    auto fill_async = [&](int t, uint32_t kb, uint32_t vb) {
        const int kv0 = t * 128;
#pragma unroll
        for (int i = 0; i < 2; ++i) {
            int idx = tid + i * 512;
            int r = idx >> 3, c8 = (idx & 7) << 3;
            cpasync16(kb + (uint32_t)((r * QSTW + (c8 >> 1)) * 4),
                      &g_Kh[((size_t)(b * NPOS) + kv0 + r) * 64 + c8]);
        }
#pragma unroll
        for (int i = 0; i < 2; ++i) {
            int idx = tid + i * 512;
            int c = idx >> 4, k8 = (idx & 15) << 3;
            cpasync16(vb + (uint32_t)((c * VSTW + (k8 >> 1)) * 4),
                      &g_Vt[((size_t)(b * 64) + c) * NPOS + kv0 + k8]);
        }
    };

    fill_async(0, kbase0, vbase0);
    CP_COMMIT();

#pragma unroll 1
    for (int t = 0; t < NQT; ++t) {
        __syncthreads();
        const int cur = t & 1;
        if (t + 1 < NQT) {
            fill_async(t + 1, kbase0 + (uint32_t)(((t + 1) & 1) * KTILE_W * 4),
                              vbase0 + (uint32_t)(((t + 1) & 1) * VTILE_W * 4));
            CP_COMMIT();
            asm volatile("cp.async.wait_group 1;" ::: "memory");
        } else {
            asm volatile("cp.async.wait_group 0;" ::: "memory");
        }
        __syncthreads();

        // tail tile (t=62) has 64 valid keys: key-half 1 has no work
        if (kh == 1 && t * 128 + 128 > NPOS) continue;

        const uint32_t kb = kbase0 + (uint32_t)(cur * KTILE_W * 4) + kLane;
        const uint32_t vb = vbase0 + (uint32_t)(cur * VTILE_W * 4) + vLane;

        // ---- S phase: 8 n-blocks over this warp's 64 keys ----
        uint32_t sfh[8][2];
#pragma unroll
        for (int nb = 0; nb < 8; ++nb) { sfh[nb][0] = 0u; sfh[nb][1] = 0u; }
#pragma unroll
        for (int k = 0; k < 4; ++k) {
#pragma unroll
            for (int j = 0; j < 4; ++j) {
                uint32_t d0, d1, d2, d3;
                ldsm4(d0, d1, d2, d3, kb + (uint32_t)((j * 16 * QSTW + 8 * k) * 4));
                mma_f16h(sfh[2 * j    ], qa[k], d0, d1, sfh[2 * j    ][0], sfh[2 * j    ][1]);
                mma_f16h(sfh[2 * j + 1], qa[k], d2, d3, sfh[2 * j + 1][0], sfh[2 * j + 1][1]);
            }
        }

        // ---- exp phase ----
        uint32_t pa[4][4];
#pragma unroll
        for (int j = 0; j < 4; ++j) {
            pa[j][0] = ex2h2(sfh[2 * j    ][0]);
            pa[j][1] = ex2h2(sfh[2 * j    ][1]);
            pa[j][2] = ex2h2(sfh[2 * j + 1][0]);
            pa[j][3] = ex2h2(sfh[2 * j + 1][1]);
        }

        // ---- PV phase: O += P @ V over this warp's 64 keys ----
#pragma unroll
        for (int j = 0; j < 4; ++j) {
            mma_f16(ofrag[8], pa[j], ONES_H2, ONES_H2, ofrag[8]);
#pragma unroll
            for (int nb2 = 0; nb2 < 4; ++nb2) {
                uint32_t v0, v1, v2, v3;
                ldsm4(v0, v1, v2, v3, vb + (uint32_t)((nb2 * 16 * VSTW + 8 * j) * 4));
                mma_f16(ofrag[2 * nb2    ], pa[j], v0, v1, ofrag[2 * nb2    ]);
                mma_f16(ofrag[2 * nb2 + 1], pa[j], v2, v3, ofrag[2 * nb2 + 1]);
            }
        }
    }

    // ---- combine the two key-halves (reuse K stages as f32 scratch) ----
    __syncthreads();                       // all compute done; stages reusable
    float* scratch = (float*)(smw + 128 * QSTW);   // [128][68] f32
    float* lsum    = scratch + 128 * 68;           // [128] f32

    const int r0 = rb + g, r1 = rb + g + 8;
    if (kh == 1) {
#pragma unroll
        for (int nb = 0; nb < 8; ++nb) {
            *(float2*)&scratch[r0 * 68 + nb * 8 + 2 * tig]
                = make_float2(ofrag[nb][0], ofrag[nb][1]);
            *(float2*)&scratch[r1 * 68 + nb * 8 + 2 * tig]
                = make_float2(ofrag[nb][2], ofrag[nb][3]);
        }
        if (tig == 0) { lsum[r0] = ofrag[8][0]; lsum[r1] = ofrag[8][2]; }
    }
    __syncthreads();

    if (kh == 0) {
        const float inv0 = 1.0f / (ofrag[8][0] + lsum[r0]);
        const float inv1 = 1.0f / (ofrag[8][2] + lsum[r1]);
        if (r0 < qrows) {
#pragma unroll
            for (int nb = 0; nb < 8; ++nb) {
                float2 s2 = *(const float2*)&scratch[r0 * 68 + nb * 8 + 2 * tig];
                *(float2*)&g_O[((b * NPOS) + n0 + r0) * 64 + nb * 8 + 2 * tig]
                    = make_float2((ofrag[nb][0] + s2.x) * inv0,
                                  (ofrag[nb][1] + s2.y) * inv0);
            }
        }
        if (r1 < qrows) {
#pragma unroll
            for (int nb = 0; nb < 8; ++nb) {
                float2 s2 = *(const float2*)&scratch[r1 * 68 + nb * 8 + 2 * tig];
                *(float2*)&g_O[((b * NPOS) + n0 + r1) * 64 + nb * 8 + 2 * tig]
                    = make_float2((ofrag[nb][2] + s2.x) * inv1,
                                  (ofrag[nb][3] + s2.y) * inv1);
            }
        }
    }
}

// ============================================================================
// Kernel C: output projection (unchanged from round 8).
// ============================================================================
__global__ __launch_bounds__(256) void out_proj_kernel(
    float* __restrict__ out,
    const float* __restrict__ wo, const float* __restrict__ bo)
{
    __shared__ float wos[4096];
    __shared__ float os[64 * 68];

    const int tid = threadIdx.x;
    const int b   = blockIdx.y;
    const int bx  = blockIdx.x;

    for (int i = tid; i < 4096; i += 256) wos[i] = wo[i];
    for (int i = tid; i < 4096; i += 256) {
        int c = i >> 6, pl = i & 63;
        os[pl * 68 + c] = g_O[((b * NPOS) + c * 125 + bx) * 64 + pl];
    }
    __syncthreads();

    const int pl = tid & 31;
    const int o0 = (tid >> 5) << 3;

    float acc[2][8];
#pragma unroll
    for (int p = 0; p < 2; ++p)
#pragma unroll
        for (int j = 0; j < 8; ++j) acc[p][j] = 0.f;

#pragma unroll 8
    for (int c = 0; c < 64; c += 4) {
        float4 xv0 = *(const float4*)&os[pl * 68 + c];
        float4 xv1 = *(const float4*)&os[(pl + 32) * 68 + c];
#pragma unroll
        for (int j = 0; j < 8; ++j) {
            float4 w4 = *(const float4*)&wos[(o0 + j) * 64 + c];
            acc[0][j] += w4.x * xv0.x + w4.y * xv0.y + w4.z * xv0.z + w4.w * xv0.w;
            acc[1][j] += w4.x * xv1.x + w4.y * xv1.y + w4.z * xv1.z + w4.w * xv1.w;
        }
    }
#pragma unroll
    for (int j = 0; j < 8; ++j) {
        float bias = bo[o0 + j];
        out[((b * 64) + o0 + j) * NPOS + bx * 64 + pl]      = acc[0][j] + bias;
        out[((b * 64) + o0 + j) * NPOS + bx * 64 + pl + 32] = acc[1][j] + bias;
    }
}

// ============================================================================
extern "C" void kernel_launch(void* const* d_in, const int* in_sizes, int n_in,
                              void* d_out, int out_size)
{
    (void)in_sizes; (void)n_in; (void)out_size;
    const float* x  = (const float*)d_in[0];
    const float* wq = (const float*)d_in[1];
    const float* bq = (const float*)d_in[2];
    const float* wk = (const float*)d_in[3];
    const float* bk = (const float*)d_in[4];
    const float* wv = (const float*)d_in[5];
    const float* bv = (const float*)d_in[6];
    const float* wo = (const float*)d_in[7];
    const float* bo = (const float*)d_in[8];
    float* out = (float*)d_out;

    const int qkv_smem = QKV2_SMEM_FLOATS * (int)sizeof(float);   // 84,736 B

    cudaFuncSetAttribute(qkv_kernel,
                         cudaFuncAttributeMaxDynamicSharedMemorySize, qkv_smem);
    cudaFuncSetAttribute(flash_mma_kernel,
                         cudaFuncAttributeMaxDynamicSharedMemorySize, FLASH_SMEM_BYTES);

    qkv_kernel<<<dim3(63, BATCH), 512, qkv_smem>>>(x, wq, bq, wk, bk, wv, bv);
    flash_mma_kernel<<<dim3(NQT, BATCH), 512, FLASH_SMEM_BYTES>>>();
    out_proj_kernel<<<dim3(125, BATCH), 256>>>(out, wo, bo);
}

// round 10
// speedup vs baseline: 1.0837x; 1.0837x over previous
#include <cuda_runtime.h>
#include <cuda_fp16.h>
#include <cstdint>

// ---------------- problem constants ----------------
#define BATCH 2
#define NPOS  8000          // 20*20*20
#define NQT   63            // ceil(8000/128); tail tile has exactly 64 keys

// -------- device scratch (padded: tail tile cp.async reads up to row 8063) --
__device__ __half g_Qh[BATCH * NPOS * 64];          // (b, n, k) pre-scaled
__device__ __half g_Kh[BATCH * NPOS * 64 + 8192];   // (b, n, k)
__device__ __half g_Vt[BATCH * 64 * NPOS + 8192];   // (b, c, n) transposed
__device__ float  g_O [BATCH * NPOS * 64];          // (b, n, c) fp32

#define QSCALE (0.125f * 1.44269504f)   // 1/sqrt(64) * log2(e), folded into Wq
#define ONES_H2 0x3C003C00u             // f16x2 {1.0, 1.0}

// ---------------- PTX helpers ----------------
__device__ __forceinline__ uint32_t smem_u32(const void* p) {
    uint32_t a;
    asm("{ .reg .u64 t; cvta.to.shared.u64 t, %1; cvt.u32.u64 %0, t; }"
        : "=r"(a) : "l"(p));
    return a;
}

__device__ __forceinline__ void mma_f16(float d[4], const uint32_t a[4],
                                        const uint32_t b0, const uint32_t b1,
                                        const float c[4]) {
    asm volatile(
        "mma.sync.aligned.m16n8k16.row.col.f32.f16.f16.f32 "
        "{%0,%1,%2,%3}, {%4,%5,%6,%7}, {%8,%9}, {%10,%11,%12,%13};"
        : "=f"(d[0]), "=f"(d[1]), "=f"(d[2]), "=f"(d[3])
        : "r"(a[0]), "r"(a[1]), "r"(a[2]), "r"(a[3]),
          "r"(b0), "r"(b1),
          "f"(c[0]), "f"(c[1]), "f"(c[2]), "f"(c[3]));
}

__device__ __forceinline__ void mma_f16h(uint32_t d[2], const uint32_t a[4],
                                         const uint32_t b0, const uint32_t b1,
                                         const uint32_t c0, const uint32_t c1) {
    asm volatile(
        "mma.sync.aligned.m16n8k16.row.col.f16.f16.f16.f16 "
        "{%0,%1}, {%2,%3,%4,%5}, {%6,%7}, {%8,%9};"
        : "=r"(d[0]), "=r"(d[1])
        : "r"(a[0]), "r"(a[1]), "r"(a[2]), "r"(a[3]),
          "r"(b0), "r"(b1), "r"(c0), "r"(c1));
}

__device__ __forceinline__ void ldsm4(uint32_t& d0, uint32_t& d1,
                                      uint32_t& d2, uint32_t& d3, uint32_t addr) {
    asm volatile("ldmatrix.sync.aligned.m8n8.x4.shared.b16 {%0,%1,%2,%3}, [%4];"
                 : "=r"(d0), "=r"(d1), "=r"(d2), "=r"(d3) : "r"(addr));
}

__device__ __forceinline__ uint32_t ex2h2(uint32_t h) {
    uint32_t r;
    asm("ex2.approx.f16x2 %0, %1;" : "=r"(r) : "r"(h));
    return r;
}

__device__ __forceinline__ void cpasync16(uint32_t dst, const void* src) {
    asm volatile("cp.async.cg.shared.global [%0], [%1], 16;" :: "r"(dst), "l"(src));
}
#define CP_COMMIT() asm volatile("cp.async.commit_group;" ::: "memory")

// ============================================================================
// Kernel A: fused QKV projection via mma.sync f16.
//   CTA = 128 positions, 256 threads (8 warps), grid (63, 2).
//   W stacked [192][64] (QSCALE folded into q rows), x tile transposed to
//   [pos][chan] f16. Warp w computes all 192 chans for positions w*16..+16
//   (96 mma). Epilogue adds bias and stages Q/K as [pos][72], V as [chan][136];
//   coalesced uint4 copy-out with tail guards (round-7 lesson).
//   smem word layout: ws[192*36] | xs[128*36] | qst[128*36] | kst[128*36]
//                     | vst[64*68] | bs[192 f32]
// ============================================================================
#define WS_OFF  0
#define XS_OFF  6912
#define QST_OFF 11520
#define KST_OFF 16128
#define VST_OFF 20736
#define BS_OFF  25088
#define QKV_SMEM_BYTES ((25088 + 192) * 4)   // 101,120 B

__global__ __launch_bounds__(256, 2) void qkv_kernel(
    const float* __restrict__ x,
    const float* __restrict__ wq, const float* __restrict__ bq,
    const float* __restrict__ wk, const float* __restrict__ bk,
    const float* __restrict__ wv, const float* __restrict__ bv)
{
    extern __shared__ uint32_t smw[];
    uint32_t* ws  = smw + WS_OFF;       // [192][36]  f16 pairs
    uint32_t* xs  = smw + XS_OFF;       // [128][36]
    __half*  qst  = (__half*)(smw + QST_OFF);   // [128][72]
    __half*  kst  = (__half*)(smw + KST_OFF);   // [128][72]
    __half*  vst  = (__half*)(smw + VST_OFF);   // [64][136]
    float*   bs   = (float*)(smw + BS_OFF);     // [192]
    const uint32_t sbase = smem_u32(smw);

    const int tid  = threadIdx.x;
    const int wid  = tid >> 5, lane = tid & 31;
    const int g    = lane >> 2, tig = lane & 3;
    const int b    = blockIdx.y;
    const int n0   = blockIdx.x * 128;
    const int p0   = wid * 16;          // this warp's 16 positions

    // ---- W fill: stacked [192][64] f16, QSCALE folded into q rows ----
    for (int i = tid; i < 6144; i += 256) {
        int row = i >> 5, c2 = i & 31;
        const float* wsrc = (row < 64) ? wq : (row < 128) ? wk : wv;
        int r = row & 63;
        float w0 = wsrc[r * 64 + 2 * c2], w1 = wsrc[r * 64 + 2 * c2 + 1];
        if (row < 64) { w0 *= QSCALE; w1 *= QSCALE; }
        __half2 h = __floats2half2_rn(w0, w1);
        ws[row * 36 + c2] = *(uint32_t*)&h;
    }
    if (tid < 192) {
        bs[tid] = (tid < 64) ? bq[tid] * QSCALE
                : (tid < 128) ? bk[tid - 64] : bv[tid - 128];
    }
    // ---- x fill: transpose (b,c,n) -> xs[pos][chan] f16 (coalesced loads) ----
    for (int i = tid; i < 4096; i += 256) {
        int c2 = i >> 7, p = i & 127;
        float x0 = 0.f, x1 = 0.f;
        if (n0 + p < NPOS) {
            x0 = x[(b * 64 + 2 * c2    ) * NPOS + n0 + p];
            x1 = x[(b * 64 + 2 * c2 + 1) * NPOS + n0 + p];
        }
        __half2 h = __floats2half2_rn(x0, x1);
        xs[p * 36 + c2] = *(uint32_t*)&h;
    }
    __syncthreads();

    // ---- B-fragments: this warp's 16 positions, all 64 k (4 chunks) ----
    const int row_in = (lane & 7) | ((lane >> 4) << 3);
    const int woff   = ((lane >> 3) & 1) << 2;
    const uint32_t xLane = sbase + (uint32_t)((XS_OFF + (p0 + row_in) * 36 + woff) * 4);
    uint32_t bfr[4][4];
#pragma unroll
    for (int kk = 0; kk < 4; ++kk)
        ldsm4(bfr[kk][0], bfr[kk][1], bfr[kk][2], bfr[kk][3],
              xLane + (uint32_t)(kk * 32));

    // A-fragment lane addressing (row-major A): row = lane&15, +16B for k-half
    const uint32_t aLaneBase = sbase
        + (uint32_t)(((lane & 15) * 36) * 4) + (uint32_t)(((lane >> 4) << 4));

    const int pA = p0 + 2 * tig;        // n-block 0 positions (pA, pA+1)
    const int pB = pA + 8;              // n-block 1

#pragma unroll
    for (int mb = 0; mb < 12; ++mb) {
        float d0[4] = {0.f, 0.f, 0.f, 0.f};
        float d1[4] = {0.f, 0.f, 0.f, 0.f};
        const uint32_t aL = aLaneBase + (uint32_t)(mb * 16 * 36 * 4);
#pragma unroll
        for (int kk = 0; kk < 4; ++kk) {
            uint32_t a[4];
            ldsm4(a[0], a[1], a[2], a[3], aL + (uint32_t)(kk * 32));
            mma_f16(d0, a, bfr[kk][0], bfr[kk][1], d0);
            mma_f16(d1, a, bfr[kk][2], bfr[kk][3], d1);
        }
        const int ch0 = mb * 16 + g, ch1 = ch0 + 8;
        const float bb0 = bs[ch0], bb1 = bs[ch1];
        if (mb < 8) {
            __half* st = (mb < 4) ? qst : kst;
            const int cc0 = ch0 & 63, cc1 = ch1 & 63;
            st[ pA      * 72 + cc0] = __float2half_rn(d0[0] + bb0);
            st[(pA + 1) * 72 + cc0] = __float2half_rn(d0[1] + bb0);
            st[ pA      * 72 + cc1] = __float2half_rn(d0[2] + bb1);
            st[(pA + 1) * 72 + cc1] = __float2half_rn(d0[3] + bb1);
            st[ pB      * 72 + cc0] = __float2half_rn(d1[0] + bb0);
            st[(pB + 1) * 72 + cc0] = __float2half_rn(d1[1] + bb0);
            st[ pB      * 72 + cc1] = __float2half_rn(d1[2] + bb1);
            st[(pB + 1) * 72 + cc1] = __float2half_rn(d1[3] + bb1);
        } else {
            const int cc0 = ch0 - 128, cc1 = ch1 - 128;
            *(__half2*)&vst[cc0 * 136 + pA] = __floats2half2_rn(d0[0] + bb0, d0[1] + bb0);
            *(__half2*)&vst[cc1 * 136 + pA] = __floats2half2_rn(d0[2] + bb1, d0[3] + bb1);
            *(__half2*)&vst[cc0 * 136 + pB] = __floats2half2_rn(d1[0] + bb0, d1[1] + bb0);
            *(__half2*)&vst[cc1 * 136 + pB] = __floats2half2_rn(d1[2] + bb1, d1[3] + bb1);
        }
    }
    __syncthreads();

    // ---- coalesced copy-out, all guarded (tail would alias: round-7 bug) ----
    for (int i = tid; i < 1024; i += 256) {
        int r = i >> 3, c8 = (i & 7) << 3;
        if (n0 + r < NPOS) {
            *(uint4*)&g_Qh[((b * NPOS) + n0 + r) * 64 + c8] =
                *(const uint4*)&qst[r * 72 + c8];
            *(uint4*)&g_Kh[((b * NPOS) + n0 + r) * 64 + c8] =
                *(const uint4*)&kst[r * 72 + c8];
        }
    }
    for (int i = tid; i < 1024; i += 256) {
        int r = i >> 4, p8 = (i & 15) << 3;
        if (n0 + p8 < NPOS)
            *(uint4*)&g_Vt[((b * 64) + r) * NPOS + n0 + p8] =
                *(const uint4*)&vst[r * 136 + p8];
    }
}

// ============================================================================
// Kernel B: flash attention — round-8 version verbatim (best measured; at the
// mma.sync HMMA throughput wall).
// ============================================================================
#define QSTW 36                 // Q/K row stride in words (72 f16)
#define VSTW 68                 // V row stride in words (136 f16)
#define KTILE_W (128 * QSTW)
#define VTILE_W (64 * VSTW)
#define FLASH_SMEM_BYTES ((128 * QSTW + 2 * KTILE_W + 2 * VTILE_W) * 4)  // 90,112

template<int JMAX>
__device__ __forceinline__ void do_tile(uint32_t kb, uint32_t vb,
                                        const uint32_t qa[4][4],
                                        float ofrag[9][4])
{
    uint32_t sfh[2 * JMAX][2];
#pragma unroll
    for (int nb = 0; nb < 2 * JMAX; ++nb) { sfh[nb][0] = 0u; sfh[nb][1] = 0u; }
#pragma unroll
    for (int k = 0; k < 4; ++k) {
#pragma unroll
        for (int j = 0; j < JMAX; ++j) {
            uint32_t d0, d1, d2, d3;
            ldsm4(d0, d1, d2, d3, kb + (uint32_t)((j * 16 * QSTW + 8 * k) * 4));
            mma_f16h(sfh[2 * j    ], qa[k], d0, d1, sfh[2 * j    ][0], sfh[2 * j    ][1]);
            mma_f16h(sfh[2 * j + 1], qa[k], d2, d3, sfh[2 * j + 1][0], sfh[2 * j + 1][1]);
        }
    }

    uint32_t pa[JMAX][4];
#pragma unroll
    for (int j = 0; j < JMAX; ++j) {
        pa[j][0] = ex2h2(sfh[2 * j    ][0]);
        pa[j][1] = ex2h2(sfh[2 * j    ][1]);
        pa[j][2] = ex2h2(sfh[2 * j + 1][0]);
        pa[j][3] = ex2h2(sfh[2 * j + 1][1]);
    }

#pragma unroll
    for (int j = 0; j < JMAX; ++j) {
        mma_f16(ofrag[8], pa[j], ONES_H2, ONES_H2, ofrag[8]);
#pragma unroll
        for (int nb2 = 0; nb2 < 4; ++nb2) {
            uint32_t v0, v1, v2, v3;
            ldsm4(v0, v1, v2, v3, vb + (uint32_t)((nb2 * 16 * VSTW + 8 * j) * 4));
            mma_f16(ofrag[2 * nb2    ], pa[j], v0, v1, ofrag[2 * nb2    ]);
            mma_f16(ofrag[2 * nb2 + 1], pa[j], v2, v3, ofrag[2 * nb2 + 1]);
        }
    }
}

__global__ __launch_bounds__(256, 1) void flash_mma_kernel()
{
    extern __shared__ uint32_t smw[];
    uint32_t* Qw = smw;                              // [128][36]
    const uint32_t sbase  = smem_u32(smw);
    const uint32_t kbase0 = sbase + 128 * QSTW * 4;
    const uint32_t vbase0 = kbase0 + 2 * KTILE_W * 4;

    const int tid  = threadIdx.x;
    const int wid  = tid >> 5, lane = tid & 31;
    const int g    = lane >> 2, tig = lane & 3;
    const int b    = blockIdx.y;
    const int n0   = blockIdx.x * 128;
    const int qrows = min(128, NPOS - n0);
    const int rb   = wid * 16;

    for (int idx = tid; idx < 128 * 8; idx += 256) {
        int r = idx >> 3, c8 = (idx & 7) << 3;
        uint4 v = make_uint4(0u, 0u, 0u, 0u);
        if (r < qrows) v = *(const uint4*)&g_Qh[((b * NPOS) + n0 + r) * 64 + c8];
        *(uint4*)&Qw[r * QSTW + (c8 >> 1)] = v;
    }
    __syncthreads();

    uint32_t qa[4][4];
#pragma unroll
    for (int k = 0; k < 4; ++k) {
        qa[k][0] = Qw[(rb + g    ) * QSTW + 8 * k + tig];
        qa[k][1] = Qw[(rb + g + 8) * QSTW + 8 * k + tig];
        qa[k][2] = Qw[(rb + g    ) * QSTW + 8 * k + tig + 4];
        qa[k][3] = Qw[(rb + g + 8) * QSTW + 8 * k + tig + 4];
    }

    const int row_in = (lane & 7) | ((lane >> 4) << 3);
    const int woff   = ((lane >> 3) & 1) << 2;
    const uint32_t kLane = (uint32_t)((row_in * QSTW + woff) * 4);
    const uint32_t vLane = (uint32_t)((row_in * VSTW + woff) * 4);

    float ofrag[9][4];
#pragma unroll
    for (int nb = 0; nb < 9; ++nb)
#pragma unroll
        for (int i = 0; i < 4; ++i) ofrag[nb][i] = 0.f;

    auto fill_async = [&](int t, uint32_t kb, uint32_t vb) {
        const int kv0 = t * 128;
#pragma unroll
        for (int i = 0; i < 4; ++i) {
            int idx = tid + i * 256;
            int r = idx >> 3, c8 = (idx & 7) << 3;
            cpasync16(kb + (uint32_t)((r * QSTW + (c8 >> 1)) * 4),
                      &g_Kh[((size_t)(b * NPOS) + kv0 + r) * 64 + c8]);
        }
#pragma unroll
        for (int i = 0; i < 4; ++i) {
            int idx = tid + i * 256;
            int c = idx >> 4, k8 = (idx & 15) << 3;
            cpasync16(vb + (uint32_t)((c * VSTW + (k8 >> 1)) * 4),
                      &g_Vt[((size_t)(b * 64) + c) * NPOS + kv0 + k8]);
        }
    };

    fill_async(0, kbase0, vbase0);
    CP_COMMIT();

#pragma unroll 1
    for (int t = 0; t < NQT; ++t) {
        __syncthreads();
        const int cur = t & 1;
        if (t + 1 < NQT) {
            fill_async(t + 1, kbase0 + (uint32_t)(((t + 1) & 1) * KTILE_W * 4),
                              vbase0 + (uint32_t)(((t + 1) & 1) * VTILE_W * 4));
            CP_COMMIT();
            asm volatile("cp.async.wait_group 1;" ::: "memory");
        } else {
            asm volatile("cp.async.wait_group 0;" ::: "memory");
        }
        __syncthreads();

        const uint32_t kb = kbase0 + (uint32_t)(cur * KTILE_W * 4) + kLane;
        const uint32_t vb = vbase0 + (uint32_t)(cur * VTILE_W * 4) + vLane;

        if (t * 128 + 128 <= NPOS) do_tile<8>(kb, vb, qa, ofrag);
        else                       do_tile<4>(kb, vb, qa, ofrag);
    }

    const float inv0 = 1.0f / ofrag[8][0];
    const float inv1 = 1.0f / ofrag[8][2];

    const int r0 = rb + g, r1 = rb + g + 8;
    if (r0 < qrows) {
#pragma unroll
        for (int nb = 0; nb < 8; ++nb)
            *(float2*)&g_O[((b * NPOS) + n0 + r0) * 64 + nb * 8 + 2 * tig]
                = make_float2(ofrag[nb][0] * inv0, ofrag[nb][1] * inv0);
    }
    if (r1 < qrows) {
#pragma unroll
        for (int nb = 0; nb < 8; ++nb)
            *(float2*)&g_O[((b * NPOS) + n0 + r1) * 64 + nb * 8 + 2 * tig]
                = make_float2(ofrag[nb][2] * inv1, ofrag[nb][3] * inv1);
    }
}

// ============================================================================
// Kernel C: output projection (round-8 version, unchanged).
// ============================================================================
__global__ __launch_bounds__(256) void out_proj_kernel(
    float* __restrict__ out,
    const float* __restrict__ wo, const float* __restrict__ bo)
{
    __shared__ float wos[4096];
    __shared__ float os[64 * 68];

    const int tid = threadIdx.x;
    const int b   = blockIdx.y;
    const int bx  = blockIdx.x;

    for (int i = tid; i < 4096; i += 256) wos[i] = wo[i];
    for (int i = tid; i < 4096; i += 256) {
        int c = i >> 6, pl = i & 63;
        os[pl * 68 + c] = g_O[((b * NPOS) + c * 125 + bx) * 64 + pl];
    }
    __syncthreads();

    const int pl = tid & 31;
    const int o0 = (tid >> 5) << 3;

    float acc[2][8];
#pragma unroll
    for (int p = 0; p < 2; ++p)
#pragma unroll
        for (int j = 0; j < 8; ++j) acc[p][j] = 0.f;

#pragma unroll 8
    for (int c = 0; c < 64; c += 4) {
        float4 xv0 = *(const float4*)&os[pl * 68 + c];
        float4 xv1 = *(const float4*)&os[(pl + 32) * 68 + c];
#pragma unroll
        for (int j = 0; j < 8; ++j) {
            float4 w4 = *(const float4*)&wos[(o0 + j) * 64 + c];
            acc[0][j] += w4.x * xv0.x + w4.y * xv0.y + w4.z * xv0.z + w4.w * xv0.w;
            acc[1][j] += w4.x * xv1.x + w4.y * xv1.y + w4.z * xv1.z + w4.w * xv1.w;
        }
    }
#pragma unroll
    for (int j = 0; j < 8; ++j) {
        float bias = bo[o0 + j];
        out[((b * 64) + o0 + j) * NPOS + bx * 64 + pl]      = acc[0][j] + bias;
        out[((b * 64) + o0 + j) * NPOS + bx * 64 + pl + 32] = acc[1][j] + bias;
    }
}

// ============================================================================
extern "C" void kernel_launch(void* const* d_in, const int* in_sizes, int n_in,
                              void* d_out, int out_size)
{
    (void)in_sizes; (void)n_in; (void)out_size;
    const float* x  = (const float*)d_in[0];
    const float* wq = (const float*)d_in[1];
    const float* bq = (const float*)d_in[2];
    const float* wk = (const float*)d_in[3];
    const float* bk = (const float*)d_in[4];
    const float* wv = (const float*)d_in[5];
    const float* bv = (const float*)d_in[6];
    const float* wo = (const float*)d_in[7];
    const float* bo = (const float*)d_in[8];
    float* out = (float*)d_out;

    cudaFuncSetAttribute(qkv_kernel,
                         cudaFuncAttributeMaxDynamicSharedMemorySize, QKV_SMEM_BYTES);
    cudaFuncSetAttribute(flash_mma_kernel,
                         cudaFuncAttributeMaxDynamicSharedMemorySize, FLASH_SMEM_BYTES);

    qkv_kernel<<<dim3(63, BATCH), 256, QKV_SMEM_BYTES>>>(x, wq, bq, wk, bk, wv, bv);
    flash_mma_kernel<<<dim3(NQT, BATCH), 256, FLASH_SMEM_BYTES>>>();
    out_proj_kernel<<<dim3(125, BATCH), 256>>>(out, wo, bo);
}

// round 11
// speedup vs baseline: 1.0931x; 1.0088x over previous
#include <cuda_runtime.h>
#include <cuda_fp16.h>
#include <cstdint>

// ---------------- problem constants ----------------
#define BATCH 2
#define NPOS  8000          // 20*20*20
#define NQT   63            // ceil(8000/128); tail tile has exactly 64 keys

// -------- device scratch (padded: tail tile cp.async reads up to row 8063) --
__device__ __half g_Qh[BATCH * NPOS * 64];          // (b, n, k) pre-scaled
__device__ __half g_Kh[BATCH * NPOS * 64 + 8192];   // (b, n, k)
__device__ __half g_Vt[BATCH * 64 * NPOS + 8192];   // (b, c, n) transposed
__device__ float  g_O [BATCH * NPOS * 64];          // (b, n, c) fp32

#define QSCALE (0.125f * 1.44269504f)   // 1/sqrt(64) * log2(e), folded into Wq

// ---------------- PTX helpers ----------------
__device__ __forceinline__ uint32_t smem_u32(const void* p) {
    uint32_t a;
    asm("{ .reg .u64 t; cvta.to.shared.u64 t, %1; cvt.u32.u64 %0, t; }"
        : "=r"(a) : "l"(p));
    return a;
}

__device__ __forceinline__ void mma_f16(float d[4], const uint32_t a[4],
                                        const uint32_t b0, const uint32_t b1,
                                        const float c[4]) {
    asm volatile(
        "mma.sync.aligned.m16n8k16.row.col.f32.f16.f16.f32 "
        "{%0,%1,%2,%3}, {%4,%5,%6,%7}, {%8,%9}, {%10,%11,%12,%13};"
        : "=f"(d[0]), "=f"(d[1]), "=f"(d[2]), "=f"(d[3])
        : "r"(a[0]), "r"(a[1]), "r"(a[2]), "r"(a[3]),
          "r"(b0), "r"(b1),
          "f"(c[0]), "f"(c[1]), "f"(c[2]), "f"(c[3]));
}

__device__ __forceinline__ void mma_f16h(uint32_t d[2], const uint32_t a[4],
                                         const uint32_t b0, const uint32_t b1,
                                         const uint32_t c0, const uint32_t c1) {
    asm volatile(
        "mma.sync.aligned.m16n8k16.row.col.f16.f16.f16.f16 "
        "{%0,%1}, {%2,%3,%4,%5}, {%6,%7}, {%8,%9};"
        : "=r"(d[0]), "=r"(d[1])
        : "r"(a[0]), "r"(a[1]), "r"(a[2]), "r"(a[3]),
          "r"(b0), "r"(b1), "r"(c0), "r"(c1));
}

__device__ __forceinline__ void ldsm4(uint32_t& d0, uint32_t& d1,
                                      uint32_t& d2, uint32_t& d3, uint32_t addr) {
    asm volatile("ldmatrix.sync.aligned.m8n8.x4.shared.b16 {%0,%1,%2,%3}, [%4];"
                 : "=r"(d0), "=r"(d1), "=r"(d2), "=r"(d3) : "r"(addr));
}

__device__ __forceinline__ uint32_t ex2h2(uint32_t h) {
    uint32_t r;
    asm("ex2.approx.f16x2 %0, %1;" : "=r"(r) : "r"(h));
    return r;
}

__device__ __forceinline__ void cpasync16(uint32_t dst, const void* src) {
    asm volatile("cp.async.cg.shared.global [%0], [%1], 16;" :: "r"(dst), "l"(src));
}
#define CP_COMMIT() asm volatile("cp.async.commit_group;" ::: "memory")

// ============================================================================
// Kernel A: fused QKV projection via mma.sync f16.
//   CTA = 64 positions, 128 threads (4 warps), grid (125, 2) -> 250 CTAs,
//   65 KB smem -> 3 CTAs resident/SM (phases of different CTAs overlap).
//   8000 % 64 == 0 -> no tail, no guards anywhere.
//   smem words: ws[192*36] | xs[64*36] | qst | kst | vst (64*36 each) | bs[192]
// ============================================================================
#define WS_OFF  0
#define XS_OFF  6912
#define QST_OFF 9216
#define KST_OFF 11520
#define VST_OFF 13824
#define BS_OFF  16128
#define QKV_SMEM_BYTES ((16128 + 192) * 4)   // 65,280 B

__global__ __launch_bounds__(128, 3) void qkv_kernel(
    const float* __restrict__ x,
    const float* __restrict__ wq, const float* __restrict__ bq,
    const float* __restrict__ wk, const float* __restrict__ bk,
    const float* __restrict__ wv, const float* __restrict__ bv)
{
    extern __shared__ uint32_t smw[];
    uint32_t* ws  = smw + WS_OFF;               // [192][36] f16 pairs
    uint32_t* xs  = smw + XS_OFF;               // [64][36]
    __half*  qst  = (__half*)(smw + QST_OFF);   // [64][72]
    __half*  kst  = (__half*)(smw + KST_OFF);   // [64][72]
    __half*  vst  = (__half*)(smw + VST_OFF);   // [64 chan][72 pos]
    float*   bs   = (float*)(smw + BS_OFF);     // [192]
    const uint32_t sbase = smem_u32(smw);

    const int tid  = threadIdx.x;
    const int wid  = tid >> 5, lane = tid & 31;
    const int g    = lane >> 2, tig = lane & 3;
    const int b    = blockIdx.y;
    const int n0   = blockIdx.x * 64;
    const int p0   = wid * 16;          // this warp's 16 positions

    // ---- W fill: stacked [192][64] f16, QSCALE folded into q rows ----
    for (int i = tid; i < 6144; i += 128) {
        int row = i >> 5, c2 = i & 31;
        const float* wsrc = (row < 64) ? wq : (row < 128) ? wk : wv;
        int r = row & 63;
        float w0 = wsrc[r * 64 + 2 * c2], w1 = wsrc[r * 64 + 2 * c2 + 1];
        if (row < 64) { w0 *= QSCALE; w1 *= QSCALE; }
        __half2 h = __floats2half2_rn(w0, w1);
        ws[row * 36 + c2] = *(uint32_t*)&h;
    }
    for (int i = tid; i < 192; i += 128) {
        bs[i] = (i < 64) ? bq[i] * QSCALE
              : (i < 128) ? bk[i - 64] : bv[i - 128];
    }
    // ---- x fill: transpose (b,c,n) -> xs[pos][chan] f16 (coalesced loads) ----
    for (int i = tid; i < 2048; i += 128) {
        int c2 = i >> 6, p = i & 63;
        float x0 = x[(b * 64 + 2 * c2    ) * NPOS + n0 + p];
        float x1 = x[(b * 64 + 2 * c2 + 1) * NPOS + n0 + p];
        __half2 h = __floats2half2_rn(x0, x1);
        xs[p * 36 + c2] = *(uint32_t*)&h;
    }
    __syncthreads();

    // ---- B-fragments: this warp's 16 positions, all 64 k (4 chunks) ----
    const int row_in = (lane & 7) | ((lane >> 4) << 3);
    const int woff   = ((lane >> 3) & 1) << 2;
    const uint32_t xLane = sbase + (uint32_t)((XS_OFF + (p0 + row_in) * 36 + woff) * 4);
    uint32_t bfr[4][4];
#pragma unroll
    for (int kk = 0; kk < 4; ++kk)
        ldsm4(bfr[kk][0], bfr[kk][1], bfr[kk][2], bfr[kk][3],
              xLane + (uint32_t)(kk * 32));

    const uint32_t aLaneBase = sbase
        + (uint32_t)(((lane & 15) * 36) * 4) + (uint32_t)(((lane >> 4) << 4));

    const int pA = p0 + 2 * tig;        // n-block 0 positions (pA, pA+1)
    const int pB = pA + 8;              // n-block 1

#pragma unroll
    for (int mb = 0; mb < 12; ++mb) {
        float d0[4] = {0.f, 0.f, 0.f, 0.f};
        float d1[4] = {0.f, 0.f, 0.f, 0.f};
        const uint32_t aL = aLaneBase + (uint32_t)(mb * 16 * 36 * 4);
#pragma unroll
        for (int kk = 0; kk < 4; ++kk) {
            uint32_t a[4];
            ldsm4(a[0], a[1], a[2], a[3], aL + (uint32_t)(kk * 32));
            mma_f16(d0, a, bfr[kk][0], bfr[kk][1], d0);
            mma_f16(d1, a, bfr[kk][2], bfr[kk][3], d1);
        }
        const int ch0 = mb * 16 + g, ch1 = ch0 + 8;
        const float bb0 = bs[ch0], bb1 = bs[ch1];
        if (mb < 8) {
            __half* st = (mb < 4) ? qst : kst;
            const int cc0 = ch0 & 63, cc1 = ch1 & 63;
            st[ pA      * 72 + cc0] = __float2half_rn(d0[0] + bb0);
            st[(pA + 1) * 72 + cc0] = __float2half_rn(d0[1] + bb0);
            st[ pA      * 72 + cc1] = __float2half_rn(d0[2] + bb1);
            st[(pA + 1) * 72 + cc1] = __float2half_rn(d0[3] + bb1);
            st[ pB      * 72 + cc0] = __float2half_rn(d1[0] + bb0);
            st[(pB + 1) * 72 + cc0] = __float2half_rn(d1[1] + bb0);
            st[ pB      * 72 + cc1] = __float2half_rn(d1[2] + bb1);
            st[(pB + 1) * 72 + cc1] = __float2half_rn(d1[3] + bb1);
        } else {
            const int cc0 = ch0 - 128, cc1 = ch1 - 128;
            *(__half2*)&vst[cc0 * 72 + pA] = __floats2half2_rn(d0[0] + bb0, d0[1] + bb0);
            *(__half2*)&vst[cc1 * 72 + pA] = __floats2half2_rn(d0[2] + bb1, d0[3] + bb1);
            *(__half2*)&vst[cc0 * 72 + pB] = __floats2half2_rn(d1[0] + bb0, d1[1] + bb0);
            *(__half2*)&vst[cc1 * 72 + pB] = __floats2half2_rn(d1[2] + bb1, d1[3] + bb1);
        }
    }
    __syncthreads();

    // ---- coalesced copy-out (no guards: 8000 % 64 == 0) ----
    for (int i = tid; i < 512; i += 128) {
        int r = i >> 3, c8 = (i & 7) << 3;
        *(uint4*)&g_Qh[((b * NPOS) + n0 + r) * 64 + c8] =
            *(const uint4*)&qst[r * 72 + c8];
        *(uint4*)&g_Kh[((b * NPOS) + n0 + r) * 64 + c8] =
            *(const uint4*)&kst[r * 72 + c8];
    }
    for (int i = tid; i < 512; i += 128) {
        int r = i >> 3, p8 = (i & 7) << 3;
        *(uint4*)&g_Vt[((b * 64) + r) * NPOS + n0 + p8] =
            *(const uint4*)&vst[r * 72 + p8];
    }
}

// ============================================================================
// Kernel B: flash attention (round-8 structure; row sums moved from the
// ones-column mma to HADD2 chains on the idle FMA pipe: -8 HMMA/warp/tile).
// ============================================================================
#define QSTW 36                 // Q/K row stride in words (72 f16)
#define VSTW 68                 // V row stride in words (136 f16)
#define KTILE_W (128 * QSTW)
#define VTILE_W (64 * VSTW)
#define FLASH_SMEM_BYTES ((128 * QSTW + 2 * KTILE_W + 2 * VTILE_W) * 4)  // 90,112

template<int JMAX>
__device__ __forceinline__ void do_tile(uint32_t kb, uint32_t vb,
                                        const uint32_t qa[4][4],
                                        float ofrag[8][4],
                                        float& lsum0, float& lsum1)
{
    // ---- S phase ----
    uint32_t sfh[2 * JMAX][2];
#pragma unroll
    for (int nb = 0; nb < 2 * JMAX; ++nb) { sfh[nb][0] = 0u; sfh[nb][1] = 0u; }
#pragma unroll
    for (int k = 0; k < 4; ++k) {
#pragma unroll
        for (int j = 0; j < JMAX; ++j) {
            uint32_t d0, d1, d2, d3;
            ldsm4(d0, d1, d2, d3, kb + (uint32_t)((j * 16 * QSTW + 8 * k) * 4));
            mma_f16h(sfh[2 * j    ], qa[k], d0, d1, sfh[2 * j    ][0], sfh[2 * j    ][1]);
            mma_f16h(sfh[2 * j + 1], qa[k], d2, d3, sfh[2 * j + 1][0], sfh[2 * j + 1][1]);
        }
    }

    // ---- exp phase ----
    uint32_t pa[JMAX][4];
#pragma unroll
    for (int j = 0; j < JMAX; ++j) {
        pa[j][0] = ex2h2(sfh[2 * j    ][0]);
        pa[j][1] = ex2h2(sfh[2 * j    ][1]);
        pa[j][2] = ex2h2(sfh[2 * j + 1][0]);
        pa[j][3] = ex2h2(sfh[2 * j + 1][1]);
    }

    // ---- row sums via HADD2 (FMA pipe; frees 8 HMMA per warp/tile) ----
    // pa[j][0], pa[j][2] hold row r0 pairs; pa[j][1], pa[j][3] hold row r1.
    {
        __half2 h0 = __floats2half2_rn(0.f, 0.f);
        __half2 h1 = h0;
#pragma unroll
        for (int j = 0; j < JMAX; ++j) {
            h0 = __hadd2(h0, *(const __half2*)&pa[j][0]);
            h0 = __hadd2(h0, *(const __half2*)&pa[j][2]);
            h1 = __hadd2(h1, *(const __half2*)&pa[j][1]);
            h1 = __hadd2(h1, *(const __half2*)&pa[j][3]);
        }
        lsum0 += __low2float(h0) + __high2float(h0);
        lsum1 += __low2float(h1) + __high2float(h1);
    }

    // ---- PV phase ----
#pragma unroll
    for (int j = 0; j < JMAX; ++j) {
#pragma unroll
        for (int nb2 = 0; nb2 < 4; ++nb2) {
            uint32_t v0, v1, v2, v3;
            ldsm4(v0, v1, v2, v3, vb + (uint32_t)((nb2 * 16 * VSTW + 8 * j) * 4));
            mma_f16(ofrag[2 * nb2    ], pa[j], v0, v1, ofrag[2 * nb2    ]);
            mma_f16(ofrag[2 * nb2 + 1], pa[j], v2, v3, ofrag[2 * nb2 + 1]);
        }
    }
}

__global__ __launch_bounds__(256, 1) void flash_mma_kernel()
{
    extern __shared__ uint32_t smw[];
    uint32_t* Qw = smw;                              // [128][36]
    const uint32_t sbase  = smem_u32(smw);
    const uint32_t kbase0 = sbase + 128 * QSTW * 4;
    const uint32_t vbase0 = kbase0 + 2 * KTILE_W * 4;

    const int tid  = threadIdx.x;
    const int wid  = tid >> 5, lane = tid & 31;
    const int g    = lane >> 2, tig = lane & 3;
    const int b    = blockIdx.y;
    const int n0   = blockIdx.x * 128;
    const int qrows = min(128, NPOS - n0);
    const int rb   = wid * 16;

    for (int idx = tid; idx < 128 * 8; idx += 256) {
        int r = idx >> 3, c8 = (idx & 7) << 3;
        uint4 v = make_uint4(0u, 0u, 0u, 0u);
        if (r < qrows) v = *(const uint4*)&g_Qh[((b * NPOS) + n0 + r) * 64 + c8];
        *(uint4*)&Qw[r * QSTW + (c8 >> 1)] = v;
    }
    __syncthreads();

    uint32_t qa[4][4];
#pragma unroll
    for (int k = 0; k < 4; ++k) {
        qa[k][0] = Qw[(rb + g    ) * QSTW + 8 * k + tig];
        qa[k][1] = Qw[(rb + g + 8) * QSTW + 8 * k + tig];
        qa[k][2] = Qw[(rb + g    ) * QSTW + 8 * k + tig + 4];
        qa[k][3] = Qw[(rb + g + 8) * QSTW + 8 * k + tig + 4];
    }

    const int row_in = (lane & 7) | ((lane >> 4) << 3);
    const int woff   = ((lane >> 3) & 1) << 2;
    const uint32_t kLane = (uint32_t)((row_in * QSTW + woff) * 4);
    const uint32_t vLane = (uint32_t)((row_in * VSTW + woff) * 4);

    float ofrag[8][4];
#pragma unroll
    for (int nb = 0; nb < 8; ++nb)
#pragma unroll
        for (int i = 0; i < 4; ++i) ofrag[nb][i] = 0.f;
    float lsum0 = 0.f, lsum1 = 0.f;

    auto fill_async = [&](int t, uint32_t kb, uint32_t vb) {
        const int kv0 = t * 128;
#pragma unroll
        for (int i = 0; i < 4; ++i) {
            int idx = tid + i * 256;
            int r = idx >> 3, c8 = (idx & 7) << 3;
            cpasync16(kb + (uint32_t)((r * QSTW + (c8 >> 1)) * 4),
                      &g_Kh[((size_t)(b * NPOS) + kv0 + r) * 64 + c8]);
        }
#pragma unroll
        for (int i = 0; i < 4; ++i) {
            int idx = tid + i * 256;
            int c = idx >> 4, k8 = (idx & 15) << 3;
            cpasync16(vb + (uint32_t)((c * VSTW + (k8 >> 1)) * 4),
                      &g_Vt[((size_t)(b * 64) + c) * NPOS + kv0 + k8]);
        }
    };

    fill_async(0, kbase0, vbase0);
    CP_COMMIT();

#pragma unroll 1
    for (int t = 0; t < NQT; ++t) {
        __syncthreads();
        const int cur = t & 1;
        if (t + 1 < NQT) {
            fill_async(t + 1, kbase0 + (uint32_t)(((t + 1) & 1) * KTILE_W * 4),
                              vbase0 + (uint32_t)(((t + 1) & 1) * VTILE_W * 4));
            CP_COMMIT();
            asm volatile("cp.async.wait_group 1;" ::: "memory");
        } else {
            asm volatile("cp.async.wait_group 0;" ::: "memory");
        }
        __syncthreads();

        const uint32_t kb = kbase0 + (uint32_t)(cur * KTILE_W * 4) + kLane;
        const uint32_t vb = vbase0 + (uint32_t)(cur * VTILE_W * 4) + vLane;

        if (t * 128 + 128 <= NPOS) do_tile<8>(kb, vb, qa, ofrag, lsum0, lsum1);
        else                       do_tile<4>(kb, vb, qa, ofrag, lsum0, lsum1);
    }

    // ---- epilogue: reduce row sums over the 4 tig lanes, normalize, store ----
    lsum0 += __shfl_xor_sync(0xffffffffu, lsum0, 1);
    lsum0 += __shfl_xor_sync(0xffffffffu, lsum0, 2);
    lsum1 += __shfl_xor_sync(0xffffffffu, lsum1, 1);
    lsum1 += __shfl_xor_sync(0xffffffffu, lsum1, 2);
    const float inv0 = 1.0f / lsum0;
    const float inv1 = 1.0f / lsum1;

    const int r0 = rb + g, r1 = rb + g + 8;
    if (r0 < qrows) {
#pragma unroll
        for (int nb = 0; nb < 8; ++nb)
            *(float2*)&g_O[((b * NPOS) + n0 + r0) * 64 + nb * 8 + 2 * tig]
                = make_float2(ofrag[nb][0] * inv0, ofrag[nb][1] * inv0);
    }
    if (r1 < qrows) {
#pragma unroll
        for (int nb = 0; nb < 8; ++nb)
            *(float2*)&g_O[((b * NPOS) + n0 + r1) * 64 + nb * 8 + 2 * tig]
                = make_float2(ofrag[nb][2] * inv1, ofrag[nb][3] * inv1);
    }
}

// ============================================================================
// Kernel C: output projection, 512 threads (1 pos x 8 chans per thread).
//   y[b,o,p] = bo[o] + sum_c wo[o,c] * O[b, c*125 + (p>>6), p&63]
// ============================================================================
__global__ __launch_bounds__(512) void out_proj_kernel(
    float* __restrict__ out,
    const float* __restrict__ wo, const float* __restrict__ bo)
{
    __shared__ float wos[4096];
    __shared__ float os[64 * 68];

    const int tid = threadIdx.x;
    const int b   = blockIdx.y;
    const int bx  = blockIdx.x;

    for (int i = tid; i < 4096; i += 512) wos[i] = wo[i];
    for (int i = tid; i < 4096; i += 512) {
        int c = i >> 6, pl = i & 63;
        os[pl * 68 + c] = g_O[((b * NPOS) + c * 125 + bx) * 64 + pl];
    }
    __syncthreads();

    const int pl = tid & 63;            // this thread's position
    const int o0 = (tid >> 6) << 3;     // 8 output channels

    float acc[8];
#pragma unroll
    for (int j = 0; j < 8; ++j) acc[j] = 0.f;

#pragma unroll 8
    for (int c = 0; c < 64; c += 4) {
        float4 xv = *(const float4*)&os[pl * 68 + c];
#pragma unroll
        for (int j = 0; j < 8; ++j) {
            float4 w4 = *(const float4*)&wos[(o0 + j) * 64 + c];   // broadcast
            acc[j] += w4.x * xv.x + w4.y * xv.y + w4.z * xv.z + w4.w * xv.w;
        }
    }
#pragma unroll
    for (int j = 0; j < 8; ++j)
        out[((b * 64) + o0 + j) * NPOS + bx * 64 + pl] = acc[j] + bo[o0 + j];
}

// ============================================================================
extern "C" void kernel_launch(void* const* d_in, const int* in_sizes, int n_in,
                              void* d_out, int out_size)
{
    (void)in_sizes; (void)n_in; (void)out_size;
    const float* x  = (const float*)d_in[0];
    const float* wq = (const float*)d_in[1];
    const float* bq = (const float*)d_in[2];
    const float* wk = (const float*)d_in[3];
    const float* bk = (const float*)d_in[4];
    const float* wv = (const float*)d_in[5];
    const float* bv = (const float*)d_in[6];
    const float* wo = (const float*)d_in[7];
    const float* bo = (const float*)d_in[8];
    float* out = (float*)d_out;

    cudaFuncSetAttribute(qkv_kernel,
                         cudaFuncAttributeMaxDynamicSharedMemorySize, QKV_SMEM_BYTES);
    cudaFuncSetAttribute(flash_mma_kernel,
                         cudaFuncAttributeMaxDynamicSharedMemorySize, FLASH_SMEM_BYTES);

    qkv_kernel<<<dim3(125, BATCH), 128, QKV_SMEM_BYTES>>>(x, wq, bq, wk, bk, wv, bv);
    flash_mma_kernel<<<dim3(NQT, BATCH), 256, FLASH_SMEM_BYTES>>>();
    out_proj_kernel<<<dim3(125, BATCH), 512>>>(out, wo, bo);
}